// round 4
// baseline (speedup 1.0000x reference)
#include <cuda_runtime.h>
#include <cstdint>
#include <cstddef>

// ---------------- problem constants (fixed by the dataset) ----------------
#define NN   16384      // nodes
#define NE   262144     // static edges (== NN * 16, also dynamic edge count)
#define DD   128        // node dim
#define DE   64         // edge dim
#define HH   256        // hidden
#define KK   16         // kNN

// ---------------- device scratch (allocation-free rule: __device__ globals) ----
__device__ float g_msg [(size_t)NE * 256];
__device__ float g_hid [(size_t)NE * 256];
__device__ float g_m   [(size_t)NE * 128];
__device__ float g_ea0 [(size_t)NE * DE];
__device__ float g_ea1 [(size_t)NE * DE];
__device__ float g_xs0 [NN * DD];
__device__ float g_xs1 [NN * DD];
__device__ float g_xd0 [NN * DD];
__device__ float g_xd1 [NN * DD];
__device__ float g_agg [NN * DD];
__device__ float g_tmpN[NN * HH];
__device__ float g_cat [NN * 2 * DD];
__device__ float g_sq  [NN];
__device__ float g_xT  [(size_t)DD * NN];
__device__ float g_dist[(size_t)NN * NN];
__device__ int   g_knn [NN * KK];
__device__ int   g_ei64flag;

// ---------------- edge_index dtype handling (int64 vs silently-int32) -----
__global__ void detect_ei_k(const void* p) {
    const unsigned long long* q = (const unsigned long long*)p;
    int ok = 1;
    #pragma unroll
    for (int i = 0; i < 8; i++)
        if (q[i] >= (unsigned long long)NN) ok = 0;
    g_ei64flag = ok;
}

__device__ __forceinline__ long long load_ei(const void* p, long long idx) {
    if (g_ei64flag) return ((const long long*)p)[idx];
    return (long long)((const int*)p)[idx];
}

// ---------------- tf32 helpers ----------------------------------------------
__device__ __forceinline__ float f2tf(float x) {
    uint32_t u;
    asm("cvt.rna.tf32.f32 %0, %1;" : "=r"(u) : "f"(x));
    return __uint_as_float(u);
}

// ---------------- 3xTF32 tensor-core GEMM (fp32-accurate) --------------------
// C = epi(A[MxK] @ B[KxN] + bias).  Requires M%128==0, N%128==0, K%32==0.
// mode 0: relu(acc + bias[col]);  mode 1: bias[col] - 2*acc (knn distances)
//
// Shared memory holds A/B tiles pre-split into (hi, lo) tf32 parts, stored in
// *fragment order* so each mma A-fragment is one LDS.128 and each B-fragment
// one LDS.64.
//   A element (r, kcol):  kk=kcol>>3, tg=kcol&3, khalf=(kcol>>2)&1,
//                         m16=r>>4, g=r&7, rhalf=(r>>3)&1, lane=g*4+tg,
//                         reg=rhalf+2*khalf
//                         idx = ((kk*8+m16)*32 + lane)*4 + reg
//   B element (kr, c):    kk=kr>>3, tg=kr&3, khalf=(kr>>2)&1,
//                         j8=c>>3, g=c&7, lane=g*4+tg
//                         idx = ((kk*16+j8)*32 + lane)*2 + khalf
#define TBM 128
#define TBN 128
#define TBK 32
#define AFHI 0
#define AFLO 4096
#define BFHI 8192
#define BFLO 12288
#define MMA3_SMEM_BYTES (16384 * 4)

__global__ __launch_bounds__(256, 2) void mma3_gemm_k(
    const float* __restrict__ A, const float* __restrict__ B,
    const float* __restrict__ bias, float* __restrict__ C,
    int M, int K, int N, int mode)
{
    extern __shared__ float sm[];

    const int tid  = threadIdx.x;
    const int lane = tid & 31;
    const int warp = tid >> 5;
    const int warp_m = warp & 1;    // 2 warps along M (64 rows each)
    const int warp_n = warp >> 1;   // 4 warps along N (32 cols each)
    const int row0 = blockIdx.y * TBM;
    const int col0 = blockIdx.x * TBN;
    const int g  = lane >> 2;       // 0..7
    const int tg = lane & 3;        // 0..3

    float acc[4][4][4];
    #pragma unroll
    for (int mm = 0; mm < 4; mm++)
        #pragma unroll
        for (int nn = 0; nn < 4; nn++)
            #pragma unroll
            for (int r = 0; r < 4; r++) acc[mm][nn][r] = 0.f;

    const int ktiles = K / TBK;
    for (int kt = 0; kt < ktiles; kt++) {
        // ---- A tile 128x32 -> fragment-order hi/lo ----
        #pragma unroll
        for (int p = 0; p < 4; p++) {
            const int lin = tid + 256 * p;
            const int r  = lin >> 3;
            const int c4 = lin & 7;
            const float4 v = *(const float4*)(A + (size_t)(row0 + r) * K + kt * TBK + c4 * 4);
            const int kk = c4 >> 1, khalf = c4 & 1;
            const int m16 = r >> 4, gg = r & 7, rhalf = (r >> 3) & 1;
            const int reg  = rhalf + (khalf << 1);
            const int base = ((kk * 8 + m16) * 32 + (gg << 2)) * 4 + reg;
            float hi, lo;
            hi = f2tf(v.x); lo = f2tf(v.x - hi); sm[AFHI + base     ] = hi; sm[AFLO + base     ] = lo;
            hi = f2tf(v.y); lo = f2tf(v.y - hi); sm[AFHI + base +  4] = hi; sm[AFLO + base +  4] = lo;
            hi = f2tf(v.z); lo = f2tf(v.z - hi); sm[AFHI + base +  8] = hi; sm[AFLO + base +  8] = lo;
            hi = f2tf(v.w); lo = f2tf(v.w - hi); sm[AFHI + base + 12] = hi; sm[AFLO + base + 12] = lo;
        }
        // ---- B tile 32x128 -> fragment-order hi/lo ----
        #pragma unroll
        for (int p = 0; p < 4; p++) {
            const int lin = tid + 256 * p;
            const int kr = lin >> 5;
            const int c4 = lin & 31;
            const float4 v = *(const float4*)(B + (size_t)(kt * TBK + kr) * N + col0 + c4 * 4);
            const int kk = kr >> 3;
            const int kw = kr & 7;
            const int tg2 = kw & 3, khalf = kw >> 2;
            const int j8 = c4 >> 1;
            const int gb = (c4 & 1) * 4;               // g of first element
            const int base = ((kk * 16 + j8) * 32 + (gb << 2) + tg2) * 2 + khalf;
            float hi, lo;
            hi = f2tf(v.x); lo = f2tf(v.x - hi); sm[BFHI + base     ] = hi; sm[BFLO + base     ] = lo;
            hi = f2tf(v.y); lo = f2tf(v.y - hi); sm[BFHI + base +  8] = hi; sm[BFLO + base +  8] = lo;
            hi = f2tf(v.z); lo = f2tf(v.z - hi); sm[BFHI + base + 16] = hi; sm[BFLO + base + 16] = lo;
            hi = f2tf(v.w); lo = f2tf(v.w - hi); sm[BFHI + base + 24] = hi; sm[BFLO + base + 24] = lo;
        }
        __syncthreads();

        #pragma unroll
        for (int kk = 0; kk < 4; kk++) {
            uint32_t af[4][4], bf[4][2];

            // load A-hi fragments (one LDS.128 each)
            #pragma unroll
            for (int mm = 0; mm < 4; mm++) {
                const float4 t = *(const float4*)&sm[AFHI + ((kk * 8 + warp_m * 4 + mm) * 32 + lane) * 4];
                af[mm][0] = __float_as_uint(t.x); af[mm][1] = __float_as_uint(t.y);
                af[mm][2] = __float_as_uint(t.z); af[mm][3] = __float_as_uint(t.w);
            }
            // pass 1: A-hi x B-lo
            #pragma unroll
            for (int nn = 0; nn < 4; nn++) {
                const float2 t = *(const float2*)&sm[BFLO + ((kk * 16 + warp_n * 4 + nn) * 32 + lane) * 2];
                bf[nn][0] = __float_as_uint(t.x); bf[nn][1] = __float_as_uint(t.y);
            }
            #pragma unroll
            for (int mm = 0; mm < 4; mm++)
                #pragma unroll
                for (int nn = 0; nn < 4; nn++)
                    asm volatile(
                        "mma.sync.aligned.m16n8k8.row.col.f32.tf32.tf32.f32 "
                        "{%0,%1,%2,%3}, {%4,%5,%6,%7}, {%8,%9}, {%0,%1,%2,%3};"
                        : "+f"(acc[mm][nn][0]), "+f"(acc[mm][nn][1]),
                          "+f"(acc[mm][nn][2]), "+f"(acc[mm][nn][3])
                        : "r"(af[mm][0]), "r"(af[mm][1]), "r"(af[mm][2]), "r"(af[mm][3]),
                          "r"(bf[nn][0]), "r"(bf[nn][1]));
            // pass 2: A-hi x B-hi
            #pragma unroll
            for (int nn = 0; nn < 4; nn++) {
                const float2 t = *(const float2*)&sm[BFHI + ((kk * 16 + warp_n * 4 + nn) * 32 + lane) * 2];
                bf[nn][0] = __float_as_uint(t.x); bf[nn][1] = __float_as_uint(t.y);
            }
            #pragma unroll
            for (int mm = 0; mm < 4; mm++)
                #pragma unroll
                for (int nn = 0; nn < 4; nn++)
                    asm volatile(
                        "mma.sync.aligned.m16n8k8.row.col.f32.tf32.tf32.f32 "
                        "{%0,%1,%2,%3}, {%4,%5,%6,%7}, {%8,%9}, {%0,%1,%2,%3};"
                        : "+f"(acc[mm][nn][0]), "+f"(acc[mm][nn][1]),
                          "+f"(acc[mm][nn][2]), "+f"(acc[mm][nn][3])
                        : "r"(af[mm][0]), "r"(af[mm][1]), "r"(af[mm][2]), "r"(af[mm][3]),
                          "r"(bf[nn][0]), "r"(bf[nn][1]));
            // pass 3: A-lo x B-hi
            #pragma unroll
            for (int mm = 0; mm < 4; mm++) {
                const float4 t = *(const float4*)&sm[AFLO + ((kk * 8 + warp_m * 4 + mm) * 32 + lane) * 4];
                af[mm][0] = __float_as_uint(t.x); af[mm][1] = __float_as_uint(t.y);
                af[mm][2] = __float_as_uint(t.z); af[mm][3] = __float_as_uint(t.w);
            }
            #pragma unroll
            for (int mm = 0; mm < 4; mm++)
                #pragma unroll
                for (int nn = 0; nn < 4; nn++)
                    asm volatile(
                        "mma.sync.aligned.m16n8k8.row.col.f32.tf32.tf32.f32 "
                        "{%0,%1,%2,%3}, {%4,%5,%6,%7}, {%8,%9}, {%0,%1,%2,%3};"
                        : "+f"(acc[mm][nn][0]), "+f"(acc[mm][nn][1]),
                          "+f"(acc[mm][nn][2]), "+f"(acc[mm][nn][3])
                        : "r"(af[mm][0]), "r"(af[mm][1]), "r"(af[mm][2]), "r"(af[mm][3]),
                          "r"(bf[nn][0]), "r"(bf[nn][1]));
        }
        __syncthreads();
    }

    // epilogue
    #pragma unroll
    for (int nn = 0; nn < 4; nn++) {
        const int col = col0 + warp_n * 32 + nn * 8 + tg * 2;
        const float bv0 = bias[col], bv1 = bias[col + 1];
        #pragma unroll
        for (int mm = 0; mm < 4; mm++) {
            const int row = row0 + warp_m * 64 + mm * 16 + g;
            float2 o0, o1;
            if (mode == 0) {
                o0.x = fmaxf(acc[mm][nn][0] + bv0, 0.f);
                o0.y = fmaxf(acc[mm][nn][1] + bv1, 0.f);
                o1.x = fmaxf(acc[mm][nn][2] + bv0, 0.f);
                o1.y = fmaxf(acc[mm][nn][3] + bv1, 0.f);
            } else {
                o0.x = bv0 - 2.f * acc[mm][nn][0];
                o0.y = bv1 - 2.f * acc[mm][nn][1];
                o1.x = bv0 - 2.f * acc[mm][nn][2];
                o1.y = bv1 - 2.f * acc[mm][nn][3];
            }
            *(float2*)(C + (size_t)row * N + col)       = o0;
            *(float2*)(C + (size_t)(row + 8) * N + col) = o1;
        }
    }
}

// ---------------- fallback SIMT GEMM (used only when N % 128 != 0) ----------
#define GBM 128
#define GBN 64
#define GBK 32

__global__ __launch_bounds__(256, 2) void gemm_k(
    const float* __restrict__ A, const float* __restrict__ B,
    const float* __restrict__ bias, float* __restrict__ C,
    int M, int K, int N, int mode)
{
    __shared__ float As[GBK][GBM + 4];
    __shared__ float Bs[GBK][GBN];
    const int tid  = threadIdx.x;
    const int row0 = blockIdx.y * GBM;
    const int col0 = blockIdx.x * GBN;
    const int tr = tid >> 4;
    const int tc = tid & 15;

    float acc[8][4];
    #pragma unroll
    for (int i = 0; i < 8; i++)
        #pragma unroll
        for (int j = 0; j < 4; j++) acc[i][j] = 0.f;

    const int ktiles = K / GBK;
    for (int kt = 0; kt < ktiles; kt++) {
        #pragma unroll
        for (int p = 0; p < 4; p++) {
            int lin = tid + 256 * p;
            int r = lin >> 3, q = lin & 7;
            const float4 v = *(const float4*)(A + (size_t)(row0 + r) * K + kt * GBK + q * 4);
            As[q * 4 + 0][r] = v.x; As[q * 4 + 1][r] = v.y;
            As[q * 4 + 2][r] = v.z; As[q * 4 + 3][r] = v.w;
        }
        #pragma unroll
        for (int p = 0; p < 2; p++) {
            int lin = tid + 256 * p;
            int kr = lin >> 4, j4 = lin & 15;
            *(float4*)&Bs[kr][j4 * 4] =
                *(const float4*)(B + (size_t)(kt * GBK + kr) * N + col0 + j4 * 4);
        }
        __syncthreads();
        #pragma unroll
        for (int k = 0; k < GBK; k++) {
            float a[8], b[4];
            *(float4*)&a[0] = *(const float4*)&As[k][tr * 8];
            *(float4*)&a[4] = *(const float4*)&As[k][tr * 8 + 4];
            *(float4*)&b[0] = *(const float4*)&Bs[k][tc * 4];
            #pragma unroll
            for (int i = 0; i < 8; i++)
                #pragma unroll
                for (int j = 0; j < 4; j++)
                    acc[i][j] = fmaf(a[i], b[j], acc[i][j]);
        }
        __syncthreads();
    }

    float bv[4];
    #pragma unroll
    for (int j = 0; j < 4; j++) bv[j] = bias[col0 + tc * 4 + j];

    #pragma unroll
    for (int i = 0; i < 8; i++) {
        const int row = row0 + tr * 8 + i;
        float4 o;
        if (mode == 0) {
            o.x = fmaxf(acc[i][0] + bv[0], 0.f);
            o.y = fmaxf(acc[i][1] + bv[1], 0.f);
            o.z = fmaxf(acc[i][2] + bv[2], 0.f);
            o.w = fmaxf(acc[i][3] + bv[3], 0.f);
        } else {
            o.x = bv[0] - 2.f * acc[i][0];
            o.y = bv[1] - 2.f * acc[i][1];
            o.z = bv[2] - 2.f * acc[i][2];
            o.w = bv[3] - 2.f * acc[i][3];
        }
        *(float4*)(C + (size_t)row * N + col0 + tc * 4) = o;
    }
}

// ---------------- small helper kernels --------------------------------------
__global__ void build_smsg_k(const float* __restrict__ ea, const float* __restrict__ xs,
                             const void* __restrict__ ei, float* __restrict__ msg)
{
    const int e = blockIdx.x, t = threadIdx.x;
    if (t < DE) {
        msg[(size_t)e * 192 + t] = ea[(size_t)e * DE + t];
    } else {
        const long long s = load_ei(ei, e);
        const long long d = load_ei(ei, (long long)NE + e);
        const int c = t - DE;
        msg[(size_t)e * 192 + t] = xs[s * DD + c] - xs[d * DD + c];
    }
}

__global__ void scatter_add_k(float* __restrict__ agg, const float* __restrict__ m,
                              const void* __restrict__ ei)
{
    const int e = blockIdx.x, t = threadIdx.x;
    const long long d = load_ei(ei, (long long)NE + e);
    atomicAdd(&agg[d * DD + t], m[(size_t)e * DD + t]);
}

__global__ void rownorm_k(const float* __restrict__ x, float* __restrict__ sq)
{
    const int row  = blockIdx.x * 8 + (threadIdx.x >> 5);
    const int lane = threadIdx.x & 31;
    const float* p = x + (size_t)row * DD;
    float s = 0.f;
    #pragma unroll
    for (int q = 0; q < 4; q++) { float v = p[lane + 32 * q]; s = fmaf(v, v, s); }
    #pragma unroll
    for (int o = 16; o > 0; o >>= 1) s += __shfl_xor_sync(0xffffffffu, s, o);
    if (lane == 0) sq[row] = s;
}

__global__ void transpose_k(const float* __restrict__ in, float* __restrict__ out)
{
    __shared__ float t[32][33];
    const int j0 = blockIdx.x * 32, k0 = blockIdx.y * 32;
    for (int r = threadIdx.y; r < 32; r += 8)
        t[r][threadIdx.x] = in[(size_t)(j0 + r) * DD + k0 + threadIdx.x];
    __syncthreads();
    for (int r = threadIdx.y; r < 32; r += 8)
        out[(size_t)(k0 + r) * NN + j0 + threadIdx.x] = t[threadIdx.x][r];
}

__global__ __launch_bounds__(256) void topk_k(const float* __restrict__ dist,
                                              int* __restrict__ knn)
{
    __shared__ float sd[256 * 16];
    __shared__ int   si[256 * 16];
    const int i = blockIdx.x, t = threadIdx.x;
    const float* row = dist + (size_t)i * NN;

    float ld[KK]; int li[KK];
    #pragma unroll
    for (int q = 0; q < KK; q++) { ld[q] = __int_as_float(0x7f800000); li[q] = 0x7FFFFFFF; }
    float worst = __int_as_float(0x7f800000); int worsti = 0x7FFFFFFF;

    for (int j = t; j < NN; j += 256) {
        const float r = row[j];
        if (r < worst || (r == worst && j < worsti)) {
            int p = KK - 1;
            while (p > 0) {
                const bool gt = (ld[p-1] > r) || (ld[p-1] == r && li[p-1] > j);
                if (!gt) break;
                ld[p] = ld[p-1]; li[p] = li[p-1]; p--;
            }
            ld[p] = r; li[p] = j;
            worst = ld[KK-1]; worsti = li[KK-1];
        }
    }
    #pragma unroll
    for (int q = 0; q < KK; q++) { sd[t * KK + q] = ld[q]; si[t * KK + q] = li[q]; }

    for (int s = 128; s > 0; s >>= 1) {
        __syncthreads();
        if (t < s) {
            float od[KK]; int oi[KK];
            int pa = t * KK, pb = (t + s) * KK;
            const int ea_ = pa + KK, eb_ = pb + KK;
            #pragma unroll
            for (int q = 0; q < KK; q++) {
                const float da = (pa < ea_) ? sd[pa] : __int_as_float(0x7f800000);
                const int   ia = (pa < ea_) ? si[pa] : 0x7FFFFFFF;
                const float db = (pb < eb_) ? sd[pb] : __int_as_float(0x7f800000);
                const int   ib = (pb < eb_) ? si[pb] : 0x7FFFFFFF;
                const bool ta = (da < db) || (da == db && ia < ib);
                if (ta) { od[q] = da; oi[q] = ia; pa++; }
                else    { od[q] = db; oi[q] = ib; pb++; }
            }
            #pragma unroll
            for (int q = 0; q < KK; q++) { sd[t * KK + q] = od[q]; si[t * KK + q] = oi[q]; }
        }
    }
    __syncthreads();
    if (t < KK) knn[i * KK + t] = si[t];
}

__global__ void build_dmsg_k(const float* __restrict__ xd, const int* __restrict__ knn,
                             float* __restrict__ msg)
{
    const int e = blockIdx.x, c = threadIdx.x;
    const int i = e >> 4;
    const int j = knn[e];
    const int cc = c & 127;
    const float xi = xd[i * DD + cc];
    const float v  = (c < DD) ? xi : (xd[j * DD + cc] - xi);
    msg[(size_t)e * 256 + c] = v;
}

__global__ void dyn_agg_k(const float* __restrict__ m, float* __restrict__ agg)
{
    const int i = blockIdx.x, d = threadIdx.x;
    const float* p = m + (size_t)i * KK * DD + d;
    float s = 0.f;
    #pragma unroll
    for (int t = 0; t < KK; t++) s += p[t * DD];
    agg[i * DD + d] = s;
}

__global__ void concat_k(const float* __restrict__ a, const float* __restrict__ b,
                         float* __restrict__ out)
{
    const int i = blockIdx.x, c = threadIdx.x;
    out[(size_t)i * 256 + c] = (c < DD) ? a[i * DD + c] : b[i * DD + c - DD];
}

// ---------------- host orchestration ---------------------------------------
static inline void gemm(const float* A, const float* B, const float* bias, float* C,
                        int M, int K, int N, int mode)
{
    if ((N % TBN) == 0 && (M % TBM) == 0) {
        dim3 g(N / TBN, M / TBM);
        mma3_gemm_k<<<g, 256, MMA3_SMEM_BYTES>>>(A, B, bias, C, M, K, N, mode);
    } else {
        dim3 g(N / GBN, M / GBM);
        gemm_k<<<g, 256>>>(A, B, bias, C, M, K, N, mode);
    }
}

extern "C" void kernel_launch(void* const* d_in, const int* in_sizes, int n_in,
                              void* d_out, int out_size)
{
    const float* x    = (const float*)d_in[0];
    const float* ea_i = (const float*)d_in[1];
    const float* sW1  = (const float*)d_in[2];
    const float* sb1  = (const float*)d_in[3];
    const float* sW2  = (const float*)d_in[4];
    const float* sb2  = (const float*)d_in[5];
    const float* uW1  = (const float*)d_in[6];
    const float* ub1  = (const float*)d_in[7];
    const float* uW2  = (const float*)d_in[8];
    const float* ub2  = (const float*)d_in[9];
    const float* rW   = (const float*)d_in[10];
    const float* rb   = (const float*)d_in[11];
    const float* dW1  = (const float*)d_in[12];
    const float* db1  = (const float*)d_in[13];
    const float* dW2  = (const float*)d_in[14];
    const float* db2  = (const float*)d_in[15];
    const float* dUW1 = (const float*)d_in[16];
    const float* dUb1 = (const float*)d_in[17];
    const float* dUW2 = (const float*)d_in[18];
    const float* dUb2 = (const float*)d_in[19];
    const float* fW1  = (const float*)d_in[20];
    const float* fb1  = (const float*)d_in[21];
    const float* fW2  = (const float*)d_in[22];
    const float* fb2  = (const float*)d_in[23];
    const void*  ei   = d_in[24];

    cudaFuncSetAttribute(mma3_gemm_k, cudaFuncAttributeMaxDynamicSharedMemorySize,
                         MMA3_SMEM_BYTES);

    float *msg, *hid, *m, *ea0, *ea1, *xs0, *xs1, *xd0, *xd1;
    float *agg, *tmpN, *cat, *sq, *xT, *dist;
    int   *knn;
    cudaGetSymbolAddress((void**)&msg,  g_msg);
    cudaGetSymbolAddress((void**)&hid,  g_hid);
    cudaGetSymbolAddress((void**)&m,    g_m);
    cudaGetSymbolAddress((void**)&ea0,  g_ea0);
    cudaGetSymbolAddress((void**)&ea1,  g_ea1);
    cudaGetSymbolAddress((void**)&xs0,  g_xs0);
    cudaGetSymbolAddress((void**)&xs1,  g_xs1);
    cudaGetSymbolAddress((void**)&xd0,  g_xd0);
    cudaGetSymbolAddress((void**)&xd1,  g_xd1);
    cudaGetSymbolAddress((void**)&agg,  g_agg);
    cudaGetSymbolAddress((void**)&tmpN, g_tmpN);
    cudaGetSymbolAddress((void**)&cat,  g_cat);
    cudaGetSymbolAddress((void**)&sq,   g_sq);
    cudaGetSymbolAddress((void**)&xT,   g_xT);
    cudaGetSymbolAddress((void**)&dist, g_dist);
    cudaGetSymbolAddress((void**)&knn,  g_knn);

    detect_ei_k<<<1, 1>>>(ei);

    // ---------------- static branch: 3 conv layers + 2 edge refiners --------
    const float* xs_in = x;
    const float* ea_in = ea_i;
    float* xs_bufs[2] = { xs0, xs1 };
    float* ea_bufs[2] = { ea0, ea1 };
    for (int i = 0; i < 3; i++) {
        build_smsg_k<<<NE, 192>>>(ea_in, xs_in, ei, msg);
        gemm(msg, sW1 + (size_t)i * 192 * HH, sb1 + i * HH, hid, NE, 192, HH, 0);
        gemm(hid, sW2 + (size_t)i * HH * DD,  sb2 + i * DD, m,   NE, HH, DD, 0);
        cudaMemsetAsync(agg, 0, (size_t)NN * DD * sizeof(float));
        scatter_add_k<<<NE, DD>>>(agg, m, ei);
        gemm(agg,  uW1 + (size_t)i * DD * HH, ub1 + i * HH, tmpN, NN, DD, HH, 0);
        float* xs_out = xs_bufs[i & 1];
        gemm(tmpN, uW2 + (size_t)i * HH * DD, ub2 + i * DD, xs_out, NN, HH, DD, 0);
        if (i < 2) {
            float* ea_out = ea_bufs[i & 1];
            gemm(ea_in, rW + (size_t)i * DE * DE, rb + i * DE, ea_out, NE, DE, DE, 0);
            ea_in = ea_out;
        }
        xs_in = xs_out;
    }

    // ---------------- dynamic branch: 2 kNN conv layers ---------------------
    const float* xd_in = x;
    float* xd_bufs[2] = { xd0, xd1 };
    for (int i = 0; i < 2; i++) {
        rownorm_k<<<NN / 8, 256>>>(xd_in, sq);
        transpose_k<<<dim3(NN / 32, DD / 32), dim3(32, 8)>>>(xd_in, xT);
        gemm(xd_in, xT, sq, dist, NN, DD, NN, 1);
        topk_k<<<NN, 256>>>(dist, knn);
        build_dmsg_k<<<NE, 256>>>(xd_in, knn, msg);
        gemm(msg, dW1 + (size_t)i * 256 * HH, db1 + i * HH, hid, NE, 256, HH, 0);
        gemm(hid, dW2 + (size_t)i * HH * DD,  db2 + i * DD, m,   NE, HH, DD, 0);
        dyn_agg_k<<<NN, DD>>>(m, agg);
        gemm(agg,  dUW1 + (size_t)i * DD * HH, dUb1 + i * HH, tmpN, NN, DD, HH, 0);
        float* xd_out = xd_bufs[i];
        gemm(tmpN, dUW2 + (size_t)i * HH * DD, dUb2 + i * DD, xd_out, NN, HH, DD, 0);
        xd_in = xd_out;
    }

    // ---------------- fuse ---------------------------------------------------
    concat_k<<<NN, 256>>>(xs_in, xd_in, cat);
    gemm(cat,  fW1, fb1, tmpN, NN, 2 * DD, HH, 0);
    gemm(tmpN, fW2, fb2, (float*)d_out, NN, HH, DD, 0);
}

// round 5
// speedup vs baseline: 1.8408x; 1.8408x over previous
#include <cuda_runtime.h>
#include <cstdint>
#include <cstddef>

// ---------------- problem constants (fixed by the dataset) ----------------
#define NN   16384      // nodes
#define NE   262144     // static edges (== NN * 16, also dynamic edge count)
#define DD   128        // node dim
#define DE   64         // edge dim
#define HH   256        // hidden
#define KK   16         // kNN

// ---------------- device scratch (allocation-free rule: __device__ globals) ----
__device__ float g_msg [(size_t)NE * 256];
__device__ float g_hid [(size_t)NE * 256];
__device__ float g_m   [(size_t)NE * 128];
__device__ float g_ea0 [(size_t)NE * DE];
__device__ float g_ea1 [(size_t)NE * DE];
__device__ float g_xs0 [NN * DD];
__device__ float g_xs1 [NN * DD];
__device__ float g_xd0 [NN * DD];
__device__ float g_xd1 [NN * DD];
__device__ float g_agg [NN * DD];
__device__ float g_tmpN[NN * HH];
__device__ float g_cat [NN * 2 * DD];
__device__ float g_sq  [NN];
__device__ float g_xT  [(size_t)DD * NN];
__device__ float g_dist[(size_t)NN * NN];
__device__ int   g_knn [NN * KK];
__device__ int   g_ei64flag;

// ---------------- edge_index dtype handling (int64 vs silently-int32) -----
__global__ void detect_ei_k(const void* p) {
    const unsigned long long* q = (const unsigned long long*)p;
    int ok = 1;
    #pragma unroll
    for (int i = 0; i < 8; i++)
        if (q[i] >= (unsigned long long)NN) ok = 0;
    g_ei64flag = ok;
}

__device__ __forceinline__ long long load_ei(const void* p, long long idx) {
    if (g_ei64flag) return ((const long long*)p)[idx];
    return (long long)((const int*)p)[idx];
}

// ---------------- tf32 helpers ----------------------------------------------
__device__ __forceinline__ float f2tf(float x) {
    uint32_t u;
    asm("cvt.rna.tf32.f32 %0, %1;" : "=r"(u) : "f"(x));
    return __uint_as_float(u);
}

// ---------------- 3xTF32 tensor-core GEMM (fp32-accurate) --------------------
// C = epi(A[MxK] @ B[KxN] + bias).  Requires M%128==0, N%128==0, K%32==0.
// mode 0: relu(acc + bias[col]);  mode 1: bias[col] - 2*acc (knn distances)
//
// Standard tile layout, duplicated hi/lo:
//   Ah/Al: [128][ASTR]  row-major (m, k)  -> STS.128 stores, conflict-free
//   Bh/Bl: [32][BSTR]   row-major (k, n)  -> STS.128 stores, conflict-free
//   Fragment reads are scalar LDS; banks 4g+tg (A) / 8tg+g (B): conflict-free.
#define TBM 128
#define TBN 128
#define TBK 32
#define ASTR 36
#define BSTR 136
#define A_SZ (TBM * ASTR)               // 4608 floats
#define B_SZ (TBK * BSTR)               // 4352 floats
#define MMA3_SMEM_BYTES ((2 * A_SZ + 2 * B_SZ) * 4)   // 71680 B

__global__ __launch_bounds__(256, 2) void mma3_gemm_k(
    const float* __restrict__ A, const float* __restrict__ B,
    const float* __restrict__ bias, float* __restrict__ C,
    int M, int K, int N, int mode)
{
    extern __shared__ float sm[];
    float* Ah = sm;
    float* Al = sm + A_SZ;
    float* Bh = sm + 2 * A_SZ;
    float* Bl = sm + 2 * A_SZ + B_SZ;

    const int tid  = threadIdx.x;
    const int lane = tid & 31;
    const int warp = tid >> 5;
    const int warp_m = warp & 1;    // 2 warps along M (64 rows each)
    const int warp_n = warp >> 1;   // 4 warps along N (32 cols each)
    const int row0 = blockIdx.y * TBM;
    const int col0 = blockIdx.x * TBN;
    const int g  = lane >> 2;       // 0..7
    const int tg = lane & 3;        // 0..3

    float acc[4][4][4];
    #pragma unroll
    for (int mm = 0; mm < 4; mm++)
        #pragma unroll
        for (int nn = 0; nn < 4; nn++)
            #pragma unroll
            for (int r = 0; r < 4; r++) acc[mm][nn][r] = 0.f;

    const int ktiles = K / TBK;
    for (int kt = 0; kt < ktiles; kt++) {
        // ---- A tile 128x32 -> hi/lo, vectorized stores ----
        #pragma unroll
        for (int p = 0; p < 4; p++) {
            const int lin = tid + 256 * p;
            const int r  = lin >> 3;
            const int c4 = lin & 7;
            const float4 v = *(const float4*)(A + (size_t)(row0 + r) * K + kt * TBK + c4 * 4);
            float4 vh, vl;
            vh.x = f2tf(v.x); vl.x = f2tf(v.x - vh.x);
            vh.y = f2tf(v.y); vl.y = f2tf(v.y - vh.y);
            vh.z = f2tf(v.z); vl.z = f2tf(v.z - vh.z);
            vh.w = f2tf(v.w); vl.w = f2tf(v.w - vh.w);
            *(float4*)&Ah[r * ASTR + c4 * 4] = vh;
            *(float4*)&Al[r * ASTR + c4 * 4] = vl;
        }
        // ---- B tile 32x128 -> hi/lo, vectorized stores ----
        #pragma unroll
        for (int p = 0; p < 4; p++) {
            const int lin = tid + 256 * p;
            const int kr = lin >> 5;
            const int c4 = lin & 31;
            const float4 v = *(const float4*)(B + (size_t)(kt * TBK + kr) * N + col0 + c4 * 4);
            float4 vh, vl;
            vh.x = f2tf(v.x); vl.x = f2tf(v.x - vh.x);
            vh.y = f2tf(v.y); vl.y = f2tf(v.y - vh.y);
            vh.z = f2tf(v.z); vl.z = f2tf(v.z - vh.z);
            vh.w = f2tf(v.w); vl.w = f2tf(v.w - vh.w);
            *(float4*)&Bh[kr * BSTR + c4 * 4] = vh;
            *(float4*)&Bl[kr * BSTR + c4 * 4] = vl;
        }
        __syncthreads();

        #pragma unroll
        for (int kk = 0; kk < 4; kk++) {
            const int kb = kk * 8;
            uint32_t af[4][4], bf[4][2];

            // A-hi fragments
            #pragma unroll
            for (int mm = 0; mm < 4; mm++) {
                const int ar = warp_m * 64 + mm * 16 + g;
                af[mm][0] = __float_as_uint(Ah[ar * ASTR + kb + tg]);
                af[mm][1] = __float_as_uint(Ah[(ar + 8) * ASTR + kb + tg]);
                af[mm][2] = __float_as_uint(Ah[ar * ASTR + kb + tg + 4]);
                af[mm][3] = __float_as_uint(Ah[(ar + 8) * ASTR + kb + tg + 4]);
            }
            // pass 1: A-hi x B-lo
            #pragma unroll
            for (int nn = 0; nn < 4; nn++) {
                const int bc = warp_n * 32 + nn * 8 + g;
                bf[nn][0] = __float_as_uint(Bl[(kb + tg) * BSTR + bc]);
                bf[nn][1] = __float_as_uint(Bl[(kb + tg + 4) * BSTR + bc]);
            }
            #pragma unroll
            for (int mm = 0; mm < 4; mm++)
                #pragma unroll
                for (int nn = 0; nn < 4; nn++)
                    asm volatile(
                        "mma.sync.aligned.m16n8k8.row.col.f32.tf32.tf32.f32 "
                        "{%0,%1,%2,%3}, {%4,%5,%6,%7}, {%8,%9}, {%0,%1,%2,%3};"
                        : "+f"(acc[mm][nn][0]), "+f"(acc[mm][nn][1]),
                          "+f"(acc[mm][nn][2]), "+f"(acc[mm][nn][3])
                        : "r"(af[mm][0]), "r"(af[mm][1]), "r"(af[mm][2]), "r"(af[mm][3]),
                          "r"(bf[nn][0]), "r"(bf[nn][1]));
            // pass 2: A-hi x B-hi
            #pragma unroll
            for (int nn = 0; nn < 4; nn++) {
                const int bc = warp_n * 32 + nn * 8 + g;
                bf[nn][0] = __float_as_uint(Bh[(kb + tg) * BSTR + bc]);
                bf[nn][1] = __float_as_uint(Bh[(kb + tg + 4) * BSTR + bc]);
            }
            #pragma unroll
            for (int mm = 0; mm < 4; mm++)
                #pragma unroll
                for (int nn = 0; nn < 4; nn++)
                    asm volatile(
                        "mma.sync.aligned.m16n8k8.row.col.f32.tf32.tf32.f32 "
                        "{%0,%1,%2,%3}, {%4,%5,%6,%7}, {%8,%9}, {%0,%1,%2,%3};"
                        : "+f"(acc[mm][nn][0]), "+f"(acc[mm][nn][1]),
                          "+f"(acc[mm][nn][2]), "+f"(acc[mm][nn][3])
                        : "r"(af[mm][0]), "r"(af[mm][1]), "r"(af[mm][2]), "r"(af[mm][3]),
                          "r"(bf[nn][0]), "r"(bf[nn][1]));
            // pass 3: A-lo x B-hi (bf still holds B-hi)
            #pragma unroll
            for (int mm = 0; mm < 4; mm++) {
                const int ar = warp_m * 64 + mm * 16 + g;
                af[mm][0] = __float_as_uint(Al[ar * ASTR + kb + tg]);
                af[mm][1] = __float_as_uint(Al[(ar + 8) * ASTR + kb + tg]);
                af[mm][2] = __float_as_uint(Al[ar * ASTR + kb + tg + 4]);
                af[mm][3] = __float_as_uint(Al[(ar + 8) * ASTR + kb + tg + 4]);
            }
            #pragma unroll
            for (int mm = 0; mm < 4; mm++)
                #pragma unroll
                for (int nn = 0; nn < 4; nn++)
                    asm volatile(
                        "mma.sync.aligned.m16n8k8.row.col.f32.tf32.tf32.f32 "
                        "{%0,%1,%2,%3}, {%4,%5,%6,%7}, {%8,%9}, {%0,%1,%2,%3};"
                        : "+f"(acc[mm][nn][0]), "+f"(acc[mm][nn][1]),
                          "+f"(acc[mm][nn][2]), "+f"(acc[mm][nn][3])
                        : "r"(af[mm][0]), "r"(af[mm][1]), "r"(af[mm][2]), "r"(af[mm][3]),
                          "r"(bf[nn][0]), "r"(bf[nn][1]));
        }
        __syncthreads();
    }

    // epilogue
    #pragma unroll
    for (int nn = 0; nn < 4; nn++) {
        const int col = col0 + warp_n * 32 + nn * 8 + tg * 2;
        const float bv0 = bias[col], bv1 = bias[col + 1];
        #pragma unroll
        for (int mm = 0; mm < 4; mm++) {
            const int row = row0 + warp_m * 64 + mm * 16 + g;
            float2 o0, o1;
            if (mode == 0) {
                o0.x = fmaxf(acc[mm][nn][0] + bv0, 0.f);
                o0.y = fmaxf(acc[mm][nn][1] + bv1, 0.f);
                o1.x = fmaxf(acc[mm][nn][2] + bv0, 0.f);
                o1.y = fmaxf(acc[mm][nn][3] + bv1, 0.f);
            } else {
                o0.x = bv0 - 2.f * acc[mm][nn][0];
                o0.y = bv1 - 2.f * acc[mm][nn][1];
                o1.x = bv0 - 2.f * acc[mm][nn][2];
                o1.y = bv1 - 2.f * acc[mm][nn][3];
            }
            *(float2*)(C + (size_t)row * N + col)       = o0;
            *(float2*)(C + (size_t)(row + 8) * N + col) = o1;
        }
    }
}

// ---------------- fallback SIMT GEMM (used only when N % 128 != 0) ----------
#define GBM 128
#define GBN 64
#define GBK 32

__global__ __launch_bounds__(256, 2) void gemm_k(
    const float* __restrict__ A, const float* __restrict__ B,
    const float* __restrict__ bias, float* __restrict__ C,
    int M, int K, int N, int mode)
{
    __shared__ float As[GBK][GBM + 4];
    __shared__ float Bs[GBK][GBN];
    const int tid  = threadIdx.x;
    const int row0 = blockIdx.y * GBM;
    const int col0 = blockIdx.x * GBN;
    const int tr = tid >> 4;
    const int tc = tid & 15;

    float acc[8][4];
    #pragma unroll
    for (int i = 0; i < 8; i++)
        #pragma unroll
        for (int j = 0; j < 4; j++) acc[i][j] = 0.f;

    const int ktiles = K / GBK;
    for (int kt = 0; kt < ktiles; kt++) {
        #pragma unroll
        for (int p = 0; p < 4; p++) {
            int lin = tid + 256 * p;
            int r = lin >> 3, q = lin & 7;
            const float4 v = *(const float4*)(A + (size_t)(row0 + r) * K + kt * GBK + q * 4);
            As[q * 4 + 0][r] = v.x; As[q * 4 + 1][r] = v.y;
            As[q * 4 + 2][r] = v.z; As[q * 4 + 3][r] = v.w;
        }
        #pragma unroll
        for (int p = 0; p < 2; p++) {
            int lin = tid + 256 * p;
            int kr = lin >> 4, j4 = lin & 15;
            *(float4*)&Bs[kr][j4 * 4] =
                *(const float4*)(B + (size_t)(kt * GBK + kr) * N + col0 + j4 * 4);
        }
        __syncthreads();
        #pragma unroll
        for (int k = 0; k < GBK; k++) {
            float a[8], b[4];
            *(float4*)&a[0] = *(const float4*)&As[k][tr * 8];
            *(float4*)&a[4] = *(const float4*)&As[k][tr * 8 + 4];
            *(float4*)&b[0] = *(const float4*)&Bs[k][tc * 4];
            #pragma unroll
            for (int i = 0; i < 8; i++)
                #pragma unroll
                for (int j = 0; j < 4; j++)
                    acc[i][j] = fmaf(a[i], b[j], acc[i][j]);
        }
        __syncthreads();
    }

    float bv[4];
    #pragma unroll
    for (int j = 0; j < 4; j++) bv[j] = bias[col0 + tc * 4 + j];

    #pragma unroll
    for (int i = 0; i < 8; i++) {
        const int row = row0 + tr * 8 + i;
        float4 o;
        if (mode == 0) {
            o.x = fmaxf(acc[i][0] + bv[0], 0.f);
            o.y = fmaxf(acc[i][1] + bv[1], 0.f);
            o.z = fmaxf(acc[i][2] + bv[2], 0.f);
            o.w = fmaxf(acc[i][3] + bv[3], 0.f);
        } else {
            o.x = bv[0] - 2.f * acc[i][0];
            o.y = bv[1] - 2.f * acc[i][1];
            o.z = bv[2] - 2.f * acc[i][2];
            o.w = bv[3] - 2.f * acc[i][3];
        }
        *(float4*)(C + (size_t)row * N + col0 + tc * 4) = o;
    }
}

// ---------------- small helper kernels --------------------------------------
__global__ void build_smsg_k(const float* __restrict__ ea, const float* __restrict__ xs,
                             const void* __restrict__ ei, float* __restrict__ msg)
{
    const int e = blockIdx.x, t = threadIdx.x;
    if (t < DE) {
        msg[(size_t)e * 192 + t] = ea[(size_t)e * DE + t];
    } else {
        const long long s = load_ei(ei, e);
        const long long d = load_ei(ei, (long long)NE + e);
        const int c = t - DE;
        msg[(size_t)e * 192 + t] = xs[s * DD + c] - xs[d * DD + c];
    }
}

__global__ void scatter_add_k(float* __restrict__ agg, const float* __restrict__ m,
                              const void* __restrict__ ei)
{
    const int e = blockIdx.x, t = threadIdx.x;
    const long long d = load_ei(ei, (long long)NE + e);
    atomicAdd(&agg[d * DD + t], m[(size_t)e * DD + t]);
}

__global__ void rownorm_k(const float* __restrict__ x, float* __restrict__ sq)
{
    const int row  = blockIdx.x * 8 + (threadIdx.x >> 5);
    const int lane = threadIdx.x & 31;
    const float* p = x + (size_t)row * DD;
    float s = 0.f;
    #pragma unroll
    for (int q = 0; q < 4; q++) { float v = p[lane + 32 * q]; s = fmaf(v, v, s); }
    #pragma unroll
    for (int o = 16; o > 0; o >>= 1) s += __shfl_xor_sync(0xffffffffu, s, o);
    if (lane == 0) sq[row] = s;
}

__global__ void transpose_k(const float* __restrict__ in, float* __restrict__ out)
{
    __shared__ float t[32][33];
    const int j0 = blockIdx.x * 32, k0 = blockIdx.y * 32;
    for (int r = threadIdx.y; r < 32; r += 8)
        t[r][threadIdx.x] = in[(size_t)(j0 + r) * DD + k0 + threadIdx.x];
    __syncthreads();
    for (int r = threadIdx.y; r < 32; r += 8)
        out[(size_t)(k0 + r) * NN + j0 + threadIdx.x] = t[threadIdx.x][r];
}

__global__ __launch_bounds__(256) void topk_k(const float* __restrict__ dist,
                                              int* __restrict__ knn)
{
    __shared__ float sd[256 * 16];
    __shared__ int   si[256 * 16];
    const int i = blockIdx.x, t = threadIdx.x;
    const float* row = dist + (size_t)i * NN;

    float ld[KK]; int li[KK];
    #pragma unroll
    for (int q = 0; q < KK; q++) { ld[q] = __int_as_float(0x7f800000); li[q] = 0x7FFFFFFF; }
    float worst = __int_as_float(0x7f800000); int worsti = 0x7FFFFFFF;

    for (int j = t; j < NN; j += 256) {
        const float r = row[j];
        if (r < worst || (r == worst && j < worsti)) {
            int p = KK - 1;
            while (p > 0) {
                const bool gt = (ld[p-1] > r) || (ld[p-1] == r && li[p-1] > j);
                if (!gt) break;
                ld[p] = ld[p-1]; li[p] = li[p-1]; p--;
            }
            ld[p] = r; li[p] = j;
            worst = ld[KK-1]; worsti = li[KK-1];
        }
    }
    #pragma unroll
    for (int q = 0; q < KK; q++) { sd[t * KK + q] = ld[q]; si[t * KK + q] = li[q]; }

    for (int s = 128; s > 0; s >>= 1) {
        __syncthreads();
        if (t < s) {
            float od[KK]; int oi[KK];
            int pa = t * KK, pb = (t + s) * KK;
            const int ea_ = pa + KK, eb_ = pb + KK;
            #pragma unroll
            for (int q = 0; q < KK; q++) {
                const float da = (pa < ea_) ? sd[pa] : __int_as_float(0x7f800000);
                const int   ia = (pa < ea_) ? si[pa] : 0x7FFFFFFF;
                const float db = (pb < eb_) ? sd[pb] : __int_as_float(0x7f800000);
                const int   ib = (pb < eb_) ? si[pb] : 0x7FFFFFFF;
                const bool ta = (da < db) || (da == db && ia < ib);
                if (ta) { od[q] = da; oi[q] = ia; pa++; }
                else    { od[q] = db; oi[q] = ib; pb++; }
            }
            #pragma unroll
            for (int q = 0; q < KK; q++) { sd[t * KK + q] = od[q]; si[t * KK + q] = oi[q]; }
        }
    }
    __syncthreads();
    if (t < KK) knn[i * KK + t] = si[t];
}

__global__ void build_dmsg_k(const float* __restrict__ xd, const int* __restrict__ knn,
                             float* __restrict__ msg)
{
    const int e = blockIdx.x, c = threadIdx.x;
    const int i = e >> 4;
    const int j = knn[e];
    const int cc = c & 127;
    const float xi = xd[i * DD + cc];
    const float v  = (c < DD) ? xi : (xd[j * DD + cc] - xi);
    msg[(size_t)e * 256 + c] = v;
}

__global__ void dyn_agg_k(const float* __restrict__ m, float* __restrict__ agg)
{
    const int i = blockIdx.x, d = threadIdx.x;
    const float* p = m + (size_t)i * KK * DD + d;
    float s = 0.f;
    #pragma unroll
    for (int t = 0; t < KK; t++) s += p[t * DD];
    agg[i * DD + d] = s;
}

__global__ void concat_k(const float* __restrict__ a, const float* __restrict__ b,
                         float* __restrict__ out)
{
    const int i = blockIdx.x, c = threadIdx.x;
    out[(size_t)i * 256 + c] = (c < DD) ? a[i * DD + c] : b[i * DD + c - DD];
}

// ---------------- host orchestration ---------------------------------------
static inline void gemm(const float* A, const float* B, const float* bias, float* C,
                        int M, int K, int N, int mode)
{
    if ((N % TBN) == 0 && (M % TBM) == 0) {
        dim3 g(N / TBN, M / TBM);
        mma3_gemm_k<<<g, 256, MMA3_SMEM_BYTES>>>(A, B, bias, C, M, K, N, mode);
    } else {
        dim3 g(N / GBN, M / GBM);
        gemm_k<<<g, 256>>>(A, B, bias, C, M, K, N, mode);
    }
}

extern "C" void kernel_launch(void* const* d_in, const int* in_sizes, int n_in,
                              void* d_out, int out_size)
{
    const float* x    = (const float*)d_in[0];
    const float* ea_i = (const float*)d_in[1];
    const float* sW1  = (const float*)d_in[2];
    const float* sb1  = (const float*)d_in[3];
    const float* sW2  = (const float*)d_in[4];
    const float* sb2  = (const float*)d_in[5];
    const float* uW1  = (const float*)d_in[6];
    const float* ub1  = (const float*)d_in[7];
    const float* uW2  = (const float*)d_in[8];
    const float* ub2  = (const float*)d_in[9];
    const float* rW   = (const float*)d_in[10];
    const float* rb   = (const float*)d_in[11];
    const float* dW1  = (const float*)d_in[12];
    const float* db1  = (const float*)d_in[13];
    const float* dW2  = (const float*)d_in[14];
    const float* db2  = (const float*)d_in[15];
    const float* dUW1 = (const float*)d_in[16];
    const float* dUb1 = (const float*)d_in[17];
    const float* dUW2 = (const float*)d_in[18];
    const float* dUb2 = (const float*)d_in[19];
    const float* fW1  = (const float*)d_in[20];
    const float* fb1  = (const float*)d_in[21];
    const float* fW2  = (const float*)d_in[22];
    const float* fb2  = (const float*)d_in[23];
    const void*  ei   = d_in[24];

    cudaFuncSetAttribute(mma3_gemm_k, cudaFuncAttributeMaxDynamicSharedMemorySize,
                         MMA3_SMEM_BYTES);

    float *msg, *hid, *m, *ea0, *ea1, *xs0, *xs1, *xd0, *xd1;
    float *agg, *tmpN, *cat, *sq, *xT, *dist;
    int   *knn;
    cudaGetSymbolAddress((void**)&msg,  g_msg);
    cudaGetSymbolAddress((void**)&hid,  g_hid);
    cudaGetSymbolAddress((void**)&m,    g_m);
    cudaGetSymbolAddress((void**)&ea0,  g_ea0);
    cudaGetSymbolAddress((void**)&ea1,  g_ea1);
    cudaGetSymbolAddress((void**)&xs0,  g_xs0);
    cudaGetSymbolAddress((void**)&xs1,  g_xs1);
    cudaGetSymbolAddress((void**)&xd0,  g_xd0);
    cudaGetSymbolAddress((void**)&xd1,  g_xd1);
    cudaGetSymbolAddress((void**)&agg,  g_agg);
    cudaGetSymbolAddress((void**)&tmpN, g_tmpN);
    cudaGetSymbolAddress((void**)&cat,  g_cat);
    cudaGetSymbolAddress((void**)&sq,   g_sq);
    cudaGetSymbolAddress((void**)&xT,   g_xT);
    cudaGetSymbolAddress((void**)&dist, g_dist);
    cudaGetSymbolAddress((void**)&knn,  g_knn);

    detect_ei_k<<<1, 1>>>(ei);

    // ---------------- static branch: 3 conv layers + 2 edge refiners --------
    const float* xs_in = x;
    const float* ea_in = ea_i;
    float* xs_bufs[2] = { xs0, xs1 };
    float* ea_bufs[2] = { ea0, ea1 };
    for (int i = 0; i < 3; i++) {
        build_smsg_k<<<NE, 192>>>(ea_in, xs_in, ei, msg);
        gemm(msg, sW1 + (size_t)i * 192 * HH, sb1 + i * HH, hid, NE, 192, HH, 0);
        gemm(hid, sW2 + (size_t)i * HH * DD,  sb2 + i * DD, m,   NE, HH, DD, 0);
        cudaMemsetAsync(agg, 0, (size_t)NN * DD * sizeof(float));
        scatter_add_k<<<NE, DD>>>(agg, m, ei);
        gemm(agg,  uW1 + (size_t)i * DD * HH, ub1 + i * HH, tmpN, NN, DD, HH, 0);
        float* xs_out = xs_bufs[i & 1];
        gemm(tmpN, uW2 + (size_t)i * HH * DD, ub2 + i * DD, xs_out, NN, HH, DD, 0);
        if (i < 2) {
            float* ea_out = ea_bufs[i & 1];
            gemm(ea_in, rW + (size_t)i * DE * DE, rb + i * DE, ea_out, NE, DE, DE, 0);
            ea_in = ea_out;
        }
        xs_in = xs_out;
    }

    // ---------------- dynamic branch: 2 kNN conv layers ---------------------
    const float* xd_in = x;
    float* xd_bufs[2] = { xd0, xd1 };
    for (int i = 0; i < 2; i++) {
        rownorm_k<<<NN / 8, 256>>>(xd_in, sq);
        transpose_k<<<dim3(NN / 32, DD / 32), dim3(32, 8)>>>(xd_in, xT);
        gemm(xd_in, xT, sq, dist, NN, DD, NN, 1);
        topk_k<<<NN, 256>>>(dist, knn);
        build_dmsg_k<<<NE, 256>>>(xd_in, knn, msg);
        gemm(msg, dW1 + (size_t)i * 256 * HH, db1 + i * HH, hid, NE, 256, HH, 0);
        gemm(hid, dW2 + (size_t)i * HH * DD,  db2 + i * DD, m,   NE, HH, DD, 0);
        dyn_agg_k<<<NN, DD>>>(m, agg);
        gemm(agg,  dUW1 + (size_t)i * DD * HH, dUb1 + i * HH, tmpN, NN, DD, HH, 0);
        float* xd_out = xd_bufs[i];
        gemm(tmpN, dUW2 + (size_t)i * HH * DD, dUb2 + i * DD, xd_out, NN, HH, DD, 0);
        xd_in = xd_out;
    }

    // ---------------- fuse ---------------------------------------------------
    concat_k<<<NN, 256>>>(xs_in, xd_in, cat);
    gemm(cat,  fW1, fb1, tmpN, NN, 2 * DD, HH, 0);
    gemm(tmpN, fW2, fb2, (float*)d_out, NN, HH, DD, 0);
}